// round 3
// baseline (speedup 1.0000x reference)
#include <cuda_runtime.h>

// ---------------------------------------------------------------------------
// Inverse DTCWT, 2 levels, fused per level (vertical in smem -> horizontal).
//   low   : (8, 256, 256, 3)
//   high0 : (8, 256, 256, 36)
//   high1 : (8, 128, 128, 36)
//   out   : (8, 512, 512, 3)
// ---------------------------------------------------------------------------

#define SCQ 0.70710678118654752f

// qshift per-phase polyphase filters; outputs n = 4k+s use window x[2k-6..2k+7]
// (window coord v = p-(2k-6)); F0 taps at v = 12+(s&1)-2j, F1 at v = 13-(s&1)-2j.
__constant__ float cF0[4][7] = {
  { 0.00325314f,  0.03466035f, -0.11720389f,  0.75614564f,  0.01186609f,  0.02382538f, -0.00543948f},
  {-0.00455690f,  0.01702522f, -0.10671180f,  0.56881042f,  0.27529538f, -0.03887280f, -0.00388321f},
  {-0.00388321f, -0.03887280f,  0.27529538f,  0.56881042f, -0.10671180f,  0.01702522f, -0.00455690f},
  {-0.00543948f,  0.02382538f,  0.01186609f,  0.75614564f, -0.11720389f,  0.03466035f,  0.00325314f}
};
__constant__ float cF1[4][7] = {
  {-0.00455690f,  0.01702522f, -0.10671180f,  0.56881042f,  0.27529538f, -0.03887280f, -0.00388321f},
  {-0.00325314f, -0.03466035f,  0.11720389f, -0.75614564f, -0.01186609f, -0.02382538f,  0.00543948f},
  { 0.00543948f, -0.02382538f, -0.01186609f, -0.75614564f,  0.11720389f, -0.03466035f, -0.00325314f},
  {-0.00388321f, -0.03887280f,  0.27529538f,  0.56881042f, -0.10671180f,  0.01702522f, -0.00455690f}
};
__constant__ float cG0[7] = {-0.0107142857142857f, -0.0535714285714286f, 0.2607142857142857f,
                              0.6071428571428571f,  0.2607142857142857f, -0.0535714285714286f,
                             -0.0107142857142857f};
__constant__ float cG1[5] = {-0.05f, -0.25f, 0.6f, -0.25f, -0.05f};

// single global intermediate: level-1 reconstruction Z (8,512,512,3)
__device__ float g_Z[8 * 512 * 512 * 3];

__device__ __forceinline__ int refl(int p, int L) {
  return p < 0 ? (-1 - p) : (p >= L ? (2 * L - 1 - p) : p);
}
__device__ __forceinline__ float comb(float x, float y, int rp, int wp) {
  return rp == 0 ? (x + y) : (wp == 0 ? (x - y) : (y - x));
}

// ---------------- KA: level 1 fused (qshift V then H) ----------------------
// block: (k, b). Produces Z rows 4k..4k+3, all 512 cols, 3 ch.
__global__ __launch_bounds__(384) void kA_lvl1(const float* __restrict__ low,
                                               const float* __restrict__ hi1) {
  __shared__ float sY1[4][768];
  __shared__ float sY2[4][768];
  int k = blockIdx.x, b = blockIdx.y;
  int t = threadIdx.x;                   // 384
  const bool interior = (k >= 3 && k <= 124);
  const int base = 2 * k - 6;

  // ---- phase 1: vertical qshift into smem (768 columns, 2 iters) ----
#pragma unroll
  for (int it = 0; it < 2; it++) {
    int u = t + it * 384;                // 0..767 = w*3+c
    int w = u / 3, c = u - 3 * w;
    int jj = w >> 1, wp = w & 1;
    const float* lowb = low + ((b * 256) * 256 + w) * 3 + c;     // + pr*768
    const float* hb   = hi1 + ((b * 128) * 128 + jj) * 36 + c;   // + i*4608

    float xl[14], xlh[14], xhl[14], xhh[14];
#pragma unroll
    for (int v = 0; v < 14; v++) {
      int p = base + v;
      int pr = interior ? p : refl(p, 256);
      xl[v] = lowb[pr * 768];
      int i = pr >> 1, rp = pr & 1;
      const float* qq = hb + i * 4608 + ((rp ^ wp) ? 18 : 0);
      xlh[v] = comb(qq[0], qq[15], rp, wp);
      xhl[v] = comb(qq[6], qq[9],  rp, wp);
      xhh[v] = comb(qq[3], qq[12], rp, wp);
    }
#pragma unroll
    for (int s = 0; s < 4; s++) {
      int v0 = 12 + (s & 1), v1 = 13 - (s & 1);
      float a = 0.f, lh = 0.f, hl = 0.f, hh = 0.f;
#pragma unroll
      for (int j = 0; j < 7; j++) {
        float f0 = cF0[s][j], f1 = cF1[s][j];
        a  += f0 * xl [v0 - 2*j];
        hl += f0 * xhl[v0 - 2*j];
        lh += f1 * xlh[v1 - 2*j];
        hh += f1 * xhh[v1 - 2*j];
      }
      sY1[s][u] = a + SCQ * lh;
      sY2[s][u] = SCQ * (hl + hh);
    }
  }
  __syncthreads();

  // ---- phase 2: horizontal qshift from smem -> g_Z (s = iteration) ----
  int k2 = t / 3, c = t - 3 * k2;        // k2 0..127
  const bool inter2 = (k2 >= 3 && k2 <= 124);
  const int base2 = 2 * k2 - 6;
  int pr2[14];
#pragma unroll
  for (int v = 0; v < 14; v++) {
    int p = base2 + v;
    pr2[v] = (inter2 ? p : refl(p, 256)) * 3 + c;
  }
#pragma unroll
  for (int s = 0; s < 4; s++) {
    float x1[14], x2[14];
#pragma unroll
    for (int v = 0; v < 14; v++) { x1[v] = sY1[s][pr2[v]]; x2[v] = sY2[s][pr2[v]]; }
    int ob = ((b * 512 + 4 * k + s) * 512 + 4 * k2) * 3 + c;
#pragma unroll
    for (int ss = 0; ss < 4; ss++) {
      int v0 = 12 + (ss & 1), v1 = 13 - (ss & 1);
      float acc = 0.f;
#pragma unroll
      for (int j = 0; j < 7; j++)
        acc += cF0[ss][j] * x1[v0 - 2*j] + cF1[ss][j] * x2[v1 - 2*j];
      g_Z[ob + ss * 3] = acc;
    }
  }
}

// ---------------- KB: level 0 fused (biort V then H) -----------------------
// block: (q, b). Produces out rows 4q..4q+3, all 512 cols, 3 ch.
__global__ __launch_bounds__(384) void kB_lvl0(const float* __restrict__ hi0,
                                               float* __restrict__ out) {
  __shared__ float sY1[4][1536];
  __shared__ float sY2[4][1536];
  int q = blockIdx.x, b = blockIdx.y;
  int t = threadIdx.x;                   // 384
  int r0 = 4 * q;
  const bool interior = (q >= 1 && q <= 125);

  // ---- phase 1: vertical biort + c2q into smem (1536 columns, 4 iters) ----
#pragma unroll
  for (int it = 0; it < 4; it++) {
    int u = t + it * 384;                // 0..1535 = w*3+c
    int w = u / 3, c = u - 3 * w;
    int jj = w >> 1, wp = w & 1;
    const float* zb = g_Z + ((b * 512) * 512 + w) * 3 + c;       // + pr*1536
    const float* hb = hi0 + ((b * 256) * 256 + jj) * 36 + c;     // + i*9216

    float xz[10], xhl[10], xlh[8], xhh[8];
#pragma unroll
    for (int v = 0; v < 10; v++) {
      int p = r0 - 3 + v;
      int pr = interior ? p : refl(p, 512);
      xz[v] = zb[pr * 1536];
      int i = pr >> 1, rp = pr & 1;
      const float* qq = hb + i * 9216 + ((rp ^ wp) ? 18 : 0);
      xhl[v] = comb(qq[6], qq[9], rp, wp);
    }
#pragma unroll
    for (int v = 0; v < 8; v++) {
      int p = r0 - 2 + v;
      int pr = interior ? p : refl(p, 512);
      int i = pr >> 1, rp = pr & 1;
      const float* qq = hb + i * 9216 + ((rp ^ wp) ? 18 : 0);
      xlh[v] = comb(qq[0], qq[15], rp, wp);
      xhh[v] = comb(qq[3], qq[12], rp, wp);
    }
#pragma unroll
    for (int s = 0; s < 4; s++) {
      float a = 0.f, hl = 0.f, lh = 0.f, hh = 0.f;
#pragma unroll
      for (int j = 0; j < 7; j++) {
        float f = cG0[j];
        a  += f * xz [s + 6 - j];
        hl += f * xhl[s + 6 - j];
      }
#pragma unroll
      for (int j = 0; j < 5; j++) {
        float f = cG1[j];
        lh += f * xlh[s + 4 - j];
        hh += f * xhh[s + 4 - j];
      }
      sY1[s][u] = a + SCQ * lh;
      sY2[s][u] = SCQ * (hl + hh);
    }
  }
  __syncthreads();

  // ---- phase 2: horizontal biort from smem -> out ----
  int qw = t / 3, c = t - 3 * qw;        // qw 0..127
  int w0 = 4 * qw;
  const bool inter2 = (qw >= 1 && qw <= 125);
  int pr1[10], pr2i[8];
#pragma unroll
  for (int v = 0; v < 10; v++) {
    int p = w0 - 3 + v;
    pr1[v] = (inter2 ? p : refl(p, 512)) * 3 + c;
  }
#pragma unroll
  for (int v = 0; v < 8; v++) {
    int p = w0 - 2 + v;
    pr2i[v] = (inter2 ? p : refl(p, 512)) * 3 + c;
  }
#pragma unroll
  for (int s = 0; s < 4; s++) {
    float x1[10], x2[8];
#pragma unroll
    for (int v = 0; v < 10; v++) x1[v] = sY1[s][pr1[v]];
#pragma unroll
    for (int v = 0; v < 8;  v++) x2[v] = sY2[s][pr2i[v]];
    int ob = ((b * 512 + r0 + s) * 512 + w0) * 3 + c;
#pragma unroll
    for (int ss = 0; ss < 4; ss++) {
      float acc = 0.f;
#pragma unroll
      for (int j = 0; j < 7; j++) acc += cG0[j] * x1[ss + 6 - j];
#pragma unroll
      for (int j = 0; j < 5; j++) acc += cG1[j] * x2[ss + 4 - j];
      out[ob + ss * 3] = acc;
    }
  }
}

extern "C" void kernel_launch(void* const* d_in, const int* in_sizes, int n_in,
                              void* d_out, int out_size) {
  const float *low = nullptr, *high0 = nullptr, *high1 = nullptr;
  for (int i = 0; i < n_in; i++) {
    if (in_sizes[i] == 8 * 256 * 256 * 3)       low   = (const float*)d_in[i];
    else if (in_sizes[i] == 8 * 256 * 256 * 36) high0 = (const float*)d_in[i];
    else if (in_sizes[i] == 8 * 128 * 128 * 36) high1 = (const float*)d_in[i];
  }
  float* out = (float*)d_out;

  kA_lvl1<<<dim3(128, 8), 384>>>(low, high1);
  kB_lvl0<<<dim3(128, 8), 384>>>(high0, out);
}

// round 5
// speedup vs baseline: 1.1062x; 1.1062x over previous
#include <cuda_runtime.h>

// ---------------------------------------------------------------------------
// Inverse DTCWT, 2 levels. 4 kernels (R2 structure), horizontal passes
// vectorized: one thread = 12 consecutive outputs (4 cols x 3 ch),
// window loaded as contiguous float4/float2 vectors.
// ---------------------------------------------------------------------------

#define SCQ 0.70710678118654752f

__constant__ float cF0[4][7] = {
  { 0.00325314f,  0.03466035f, -0.11720389f,  0.75614564f,  0.01186609f,  0.02382538f, -0.00543948f},
  {-0.00455690f,  0.01702522f, -0.10671180f,  0.56881042f,  0.27529538f, -0.03887280f, -0.00388321f},
  {-0.00388321f, -0.03887280f,  0.27529538f,  0.56881042f, -0.10671180f,  0.01702522f, -0.00455690f},
  {-0.00543948f,  0.02382538f,  0.01186609f,  0.75614564f, -0.11720389f,  0.03466035f,  0.00325314f}
};
__constant__ float cF1[4][7] = {
  {-0.00455690f,  0.01702522f, -0.10671180f,  0.56881042f,  0.27529538f, -0.03887280f, -0.00388321f},
  {-0.00325314f, -0.03466035f,  0.11720389f, -0.75614564f, -0.01186609f, -0.02382538f,  0.00543948f},
  { 0.00543948f, -0.02382538f, -0.01186609f, -0.75614564f,  0.11720389f, -0.03466035f, -0.00325314f},
  {-0.00388321f, -0.03887280f,  0.27529538f,  0.56881042f, -0.10671180f,  0.01702522f, -0.00455690f}
};
__constant__ float cG0[7] = {-0.0107142857142857f, -0.0535714285714286f, 0.2607142857142857f,
                              0.6071428571428571f,  0.2607142857142857f, -0.0535714285714286f,
                             -0.0107142857142857f};
__constant__ float cG1[5] = {-0.05f, -0.25f, 0.6f, -0.25f, -0.05f};

// scratch
__device__ float g_Y1 [8 * 512 * 256 * 3];
__device__ float g_Y2 [8 * 512 * 256 * 3];
__device__ float g_Z  [8 * 512 * 512 * 3];
__device__ float g_Y1b[8 * 512 * 512 * 3];
__device__ float g_Y2b[8 * 512 * 512 * 3];

__device__ __forceinline__ int refl(int p, int L) {
  return p < 0 ? (-1 - p) : (p >= L ? (2 * L - 1 - p) : p);
}
__device__ __forceinline__ float comb(float x, float y, int rp, int wp) {
  return rp == 0 ? (x + y) : (wp == 0 ? (x - y) : (y - x));
}

// ---------------- K1: level-1 vertical (qshift over H), per-thread 4 rows ---
__global__ void k1_lvl1_vert(const float* __restrict__ low, const float* __restrict__ hi1) {
  int u = blockIdx.x * 256 + threadIdx.x;   // 0..767 = 3*w+c
  int k = blockIdx.y;                        // 0..127
  int b = blockIdx.z;
  int w = u / 3, c = u - 3 * w;
  int jj = w >> 1, wp = w & 1;
  const bool interior = (k >= 3 && k <= 124);
  const int base = 2 * k - 6;

  const float* lowb = low + ((b * 256) * 256 + w) * 3 + c;
  const float* hb   = hi1 + ((b * 128) * 128 + jj) * 36 + c;

  float xl[14], xlh[14], xhl[14], xhh[14];
#pragma unroll
  for (int v = 0; v < 14; v++) {
    int p = base + v;
    int pr = interior ? p : refl(p, 256);
    xl[v] = lowb[pr * 768];
    int i = pr >> 1, rp = pr & 1;
    const float* q = hb + i * 4608 + ((rp ^ wp) ? 18 : 0);
    xlh[v] = comb(q[0], q[15], rp, wp);
    xhl[v] = comb(q[6], q[9],  rp, wp);
    xhh[v] = comb(q[3], q[12], rp, wp);
  }
  int ob = ((b * 512 + 4 * k) * 256 + w) * 3 + c;
#pragma unroll
  for (int s = 0; s < 4; s++) {
    int v0 = 12 + (s & 1), v1 = 13 - (s & 1);
    float a = 0.f, lh = 0.f, hl = 0.f, hh = 0.f;
#pragma unroll
    for (int j = 0; j < 7; j++) {
      float f0 = cF0[s][j], f1 = cF1[s][j];
      a  += f0 * xl [v0 - 2*j];
      hl += f0 * xhl[v0 - 2*j];
      lh += f1 * xlh[v1 - 2*j];
      hh += f1 * xhh[v1 - 2*j];
    }
    g_Y1[ob + s * 768] = a + SCQ * lh;
    g_Y2[ob + s * 768] = SCQ * (hl + hh);
  }
}

// ---------------- K2: level-1 horizontal (qshift over W), vectorized --------
// thread: (b,h,k) -> 12 consecutive Z floats; window 14 cols x3 = 42 floats/array
__global__ __launch_bounds__(256, 4) void k2_lvl1_horz() {
  int idx = blockIdx.x * 256 + threadIdx.x;
  int k = idx & 127;
  int h = (idx >> 7) & 511;
  int b = idx >> 16;
  const bool interior = (k >= 3 && k <= 124);
  int rb  = ((b * 512 + h) * 256) * 3;          // Y row base
  int rb2 = ((b * 512 + h) * 512) * 3;          // Z row base

  float O[12];
#pragma unroll
  for (int i = 0; i < 12; i++) O[i] = 0.f;

  {
    float X1[42];
    if (interior) {
      const float2* p2 = (const float2*)(g_Y1 + rb + 6 * k - 18);
#pragma unroll
      for (int m = 0; m < 21; m++) ((float2*)X1)[m] = p2[m];
    } else {
#pragma unroll
      for (int v = 0; v < 14; v++) {
        int pr = refl(2 * k - 6 + v, 256);
#pragma unroll
        for (int c = 0; c < 3; c++) X1[v * 3 + c] = g_Y1[rb + pr * 3 + c];
      }
    }
#pragma unroll
    for (int s = 0; s < 4; s++) {
      int v0 = 12 + (s & 1);
#pragma unroll
      for (int j = 0; j < 7; j++) {
        float f = cF0[s][j];
#pragma unroll
        for (int c = 0; c < 3; c++) O[s * 3 + c] += f * X1[(v0 - 2 * j) * 3 + c];
      }
    }
  }
  {
    float X2[42];
    if (interior) {
      const float2* p2 = (const float2*)(g_Y2 + rb + 6 * k - 18);
#pragma unroll
      for (int m = 0; m < 21; m++) ((float2*)X2)[m] = p2[m];
    } else {
#pragma unroll
      for (int v = 0; v < 14; v++) {
        int pr = refl(2 * k - 6 + v, 256);
#pragma unroll
        for (int c = 0; c < 3; c++) X2[v * 3 + c] = g_Y2[rb + pr * 3 + c];
      }
    }
#pragma unroll
    for (int s = 0; s < 4; s++) {
      int v1 = 13 - (s & 1);
#pragma unroll
      for (int j = 0; j < 7; j++) {
        float f = cF1[s][j];
#pragma unroll
        for (int c = 0; c < 3; c++) O[s * 3 + c] += f * X2[(v1 - 2 * j) * 3 + c];
      }
    }
  }
  float4* po = (float4*)(g_Z + rb2 + 12 * k);
#pragma unroll
  for (int m = 0; m < 3; m++)
    po[m] = make_float4(O[4 * m], O[4 * m + 1], O[4 * m + 2], O[4 * m + 3]);
}

// ---------------- K3: level-0 vertical (biort over H), per-thread 4 rows ----
__global__ void k3_lvl0_vert(const float* __restrict__ hi0) {
  int u = blockIdx.x * 256 + threadIdx.x;   // 0..1535
  int q = blockIdx.y;                        // 0..127
  int b = blockIdx.z;
  int w = u / 3, c = u - 3 * w;
  int jj = w >> 1, wp = w & 1;
  int r0 = 4 * q;
  const bool interior = (q >= 1 && q <= 125);

  const float* zb = g_Z + ((b * 512) * 512 + w) * 3 + c;
  const float* hb = hi0 + ((b * 256) * 256 + jj) * 36 + c;

  float xz[10], xhl[10], xlh[8], xhh[8];
#pragma unroll
  for (int v = 0; v < 10; v++) {
    int p = r0 - 3 + v;
    int pr = interior ? p : refl(p, 512);
    xz[v] = zb[pr * 1536];
    int i = pr >> 1, rp = pr & 1;
    const float* qq = hb + i * 9216 + ((rp ^ wp) ? 18 : 0);
    xhl[v] = comb(qq[6], qq[9], rp, wp);
  }
#pragma unroll
  for (int v = 0; v < 8; v++) {
    int p = r0 - 2 + v;
    int pr = interior ? p : refl(p, 512);
    int i = pr >> 1, rp = pr & 1;
    const float* qq = hb + i * 9216 + ((rp ^ wp) ? 18 : 0);
    xlh[v] = comb(qq[0], qq[15], rp, wp);
    xhh[v] = comb(qq[3], qq[12], rp, wp);
  }
  int ob = ((b * 512 + r0) * 512 + w) * 3 + c;
#pragma unroll
  for (int s = 0; s < 4; s++) {
    float a = 0.f, hl = 0.f, lh = 0.f, hh = 0.f;
#pragma unroll
    for (int j = 0; j < 7; j++) {
      float f = cG0[j];
      a  += f * xz [s + 6 - j];
      hl += f * xhl[s + 6 - j];
    }
#pragma unroll
    for (int j = 0; j < 5; j++) {
      float f = cG1[j];
      lh += f * xlh[s + 4 - j];
      hh += f * xhh[s + 4 - j];
    }
    g_Y1b[ob + s * 1536] = a + SCQ * lh;
    g_Y2b[ob + s * 1536] = SCQ * (hl + hh);
  }
}

// ---------------- K4: level-0 horizontal (biort over W), vectorized ---------
// thread: (b,h,q) -> 12 consecutive out floats; window cols w0-4..w0+7 = 36 floats/array
__global__ __launch_bounds__(256, 4) void k4_lvl0_horz(float* __restrict__ out) {
  int idx = blockIdx.x * 256 + threadIdx.x;
  int q = idx & 127;
  int h = (idx >> 7) & 511;
  int b = idx >> 16;
  int w0 = 4 * q;
  const bool interior = (q >= 1 && q <= 126);
  int rb = ((b * 512 + h) * 512) * 3;

  float O[12];
#pragma unroll
  for (int i = 0; i < 12; i++) O[i] = 0.f;

  {
    float A[36];
    if (interior) {
      const float4* p4 = (const float4*)(g_Y1b + rb + 12 * q - 12);
#pragma unroll
      for (int m = 0; m < 9; m++) ((float4*)A)[m] = p4[m];
    } else {
#pragma unroll
      for (int m = 0; m < 12; m++) {
        int pr = refl(w0 - 4 + m, 512);
#pragma unroll
        for (int c = 0; c < 3; c++) A[m * 3 + c] = g_Y1b[rb + pr * 3 + c];
      }
    }
#pragma unroll
    for (int s = 0; s < 4; s++)
#pragma unroll
      for (int j = 0; j < 7; j++) {
        float f = cG0[j];
#pragma unroll
        for (int c = 0; c < 3; c++) O[s * 3 + c] += f * A[(s + 7 - j) * 3 + c];
      }
  }
  {
    float B[36];
    if (interior) {
      const float4* p4 = (const float4*)(g_Y2b + rb + 12 * q - 12);
#pragma unroll
      for (int m = 0; m < 9; m++) ((float4*)B)[m] = p4[m];
    } else {
#pragma unroll
      for (int m = 0; m < 12; m++) {
        int pr = refl(w0 - 4 + m, 512);
#pragma unroll
        for (int c = 0; c < 3; c++) B[m * 3 + c] = g_Y2b[rb + pr * 3 + c];
      }
    }
#pragma unroll
    for (int s = 0; s < 4; s++)
#pragma unroll
      for (int j = 0; j < 5; j++) {
        float f = cG1[j];
#pragma unroll
        for (int c = 0; c < 3; c++) O[s * 3 + c] += f * B[(s + 6 - j) * 3 + c];
      }
  }
  float4* po = (float4*)(out + rb + 12 * q);
#pragma unroll
  for (int m = 0; m < 3; m++)
    po[m] = make_float4(O[4 * m], O[4 * m + 1], O[4 * m + 2], O[4 * m + 3]);
}

extern "C" void kernel_launch(void* const* d_in, const int* in_sizes, int n_in,
                              void* d_out, int out_size) {
  const float *low = nullptr, *high0 = nullptr, *high1 = nullptr;
  for (int i = 0; i < n_in; i++) {
    if (in_sizes[i] == 8 * 256 * 256 * 3)       low   = (const float*)d_in[i];
    else if (in_sizes[i] == 8 * 256 * 256 * 36) high0 = (const float*)d_in[i];
    else if (in_sizes[i] == 8 * 128 * 128 * 36) high1 = (const float*)d_in[i];
  }
  float* out = (float*)d_out;

  k1_lvl1_vert<<<dim3(3, 128, 8), 256>>>(low, high1);
  k2_lvl1_horz<<<2048, 256>>>();          // 524288 threads = 8*512*128
  k3_lvl0_vert<<<dim3(6, 128, 8), 256>>>(high0);
  k4_lvl0_horz<<<2048, 256>>>(out);       // 524288 threads = 8*512*128 (FIXED: was 8192)
}

// round 6
// speedup vs baseline: 1.2158x; 1.0991x over previous
#include <cuda_runtime.h>

// ---------------------------------------------------------------------------
// Inverse DTCWT, 2 levels.
//   k1/k2: level-1 qshift (vertical, then horizontal) via g_Y1/g_Y2 -> g_Z
//   kB   : level-0 biort, fused tiled (vertical->smem->horizontal) -> out
// ---------------------------------------------------------------------------

#define SCQ 0.70710678118654752f

__constant__ float cF0[4][7] = {
  { 0.00325314f,  0.03466035f, -0.11720389f,  0.75614564f,  0.01186609f,  0.02382538f, -0.00543948f},
  {-0.00455690f,  0.01702522f, -0.10671180f,  0.56881042f,  0.27529538f, -0.03887280f, -0.00388321f},
  {-0.00388321f, -0.03887280f,  0.27529538f,  0.56881042f, -0.10671180f,  0.01702522f, -0.00455690f},
  {-0.00543948f,  0.02382538f,  0.01186609f,  0.75614564f, -0.11720389f,  0.03466035f,  0.00325314f}
};
__constant__ float cF1[4][7] = {
  {-0.00455690f,  0.01702522f, -0.10671180f,  0.56881042f,  0.27529538f, -0.03887280f, -0.00388321f},
  {-0.00325314f, -0.03466035f,  0.11720389f, -0.75614564f, -0.01186609f, -0.02382538f,  0.00543948f},
  { 0.00543948f, -0.02382538f, -0.01186609f, -0.75614564f,  0.11720389f, -0.03466035f, -0.00325314f},
  {-0.00388321f, -0.03887280f,  0.27529538f,  0.56881042f, -0.10671180f,  0.01702522f, -0.00455690f}
};
__constant__ float cG0[7] = {-0.0107142857142857f, -0.0535714285714286f, 0.2607142857142857f,
                              0.6071428571428571f,  0.2607142857142857f, -0.0535714285714286f,
                             -0.0107142857142857f};
__constant__ float cG1[5] = {-0.05f, -0.25f, 0.6f, -0.25f, -0.05f};

// scratch
__device__ float g_Y1[8 * 512 * 256 * 3];
__device__ float g_Y2[8 * 512 * 256 * 3];
__device__ float g_Z [8 * 512 * 512 * 3];

__device__ __forceinline__ int refl(int p, int L) {
  return p < 0 ? (-1 - p) : (p >= L ? (2 * L - 1 - p) : p);
}
__device__ __forceinline__ float comb(float x, float y, int rp, int wp) {
  return rp == 0 ? (x + y) : (wp == 0 ? (x - y) : (y - x));
}

// ---------------- K1: level-1 vertical (qshift over H), per-thread 4 rows ---
__global__ void k1_lvl1_vert(const float* __restrict__ low, const float* __restrict__ hi1) {
  int u = blockIdx.x * 256 + threadIdx.x;   // 0..767 = 3*w+c
  int k = blockIdx.y;                        // 0..127
  int b = blockIdx.z;
  int w = u / 3, c = u - 3 * w;
  int jj = w >> 1, wp = w & 1;
  const bool interior = (k >= 3 && k <= 124);
  const int base = 2 * k - 6;

  const float* lowb = low + ((b * 256) * 256 + w) * 3 + c;
  const float* hb   = hi1 + ((b * 128) * 128 + jj) * 36 + c;

  float xl[14], xlh[14], xhl[14], xhh[14];
#pragma unroll
  for (int v = 0; v < 14; v++) {
    int p = base + v;
    int pr = interior ? p : refl(p, 256);
    xl[v] = lowb[pr * 768];
    int i = pr >> 1, rp = pr & 1;
    const float* q = hb + i * 4608 + ((rp ^ wp) ? 18 : 0);
    xlh[v] = comb(q[0], q[15], rp, wp);
    xhl[v] = comb(q[6], q[9],  rp, wp);
    xhh[v] = comb(q[3], q[12], rp, wp);
  }
  int ob = ((b * 512 + 4 * k) * 256 + w) * 3 + c;
#pragma unroll
  for (int s = 0; s < 4; s++) {
    int v0 = 12 + (s & 1), v1 = 13 - (s & 1);
    float a = 0.f, lh = 0.f, hl = 0.f, hh = 0.f;
#pragma unroll
    for (int j = 0; j < 7; j++) {
      float f0 = cF0[s][j], f1 = cF1[s][j];
      a  += f0 * xl [v0 - 2*j];
      hl += f0 * xhl[v0 - 2*j];
      lh += f1 * xlh[v1 - 2*j];
      hh += f1 * xhh[v1 - 2*j];
    }
    g_Y1[ob + s * 768] = a + SCQ * lh;
    g_Y2[ob + s * 768] = SCQ * (hl + hh);
  }
}

// ---------------- K2: level-1 horizontal (qshift over W), vectorized --------
__global__ __launch_bounds__(256, 4) void k2_lvl1_horz() {
  int idx = blockIdx.x * 256 + threadIdx.x;
  int k = idx & 127;
  int h = (idx >> 7) & 511;
  int b = idx >> 16;
  const bool interior = (k >= 3 && k <= 124);
  int rb  = ((b * 512 + h) * 256) * 3;
  int rb2 = ((b * 512 + h) * 512) * 3;

  float O[12];
#pragma unroll
  for (int i = 0; i < 12; i++) O[i] = 0.f;

  {
    float X1[42];
    if (interior) {
      const float2* p2 = (const float2*)(g_Y1 + rb + 6 * k - 18);
#pragma unroll
      for (int m = 0; m < 21; m++) ((float2*)X1)[m] = p2[m];
    } else {
#pragma unroll
      for (int v = 0; v < 14; v++) {
        int pr = refl(2 * k - 6 + v, 256);
#pragma unroll
        for (int c = 0; c < 3; c++) X1[v * 3 + c] = g_Y1[rb + pr * 3 + c];
      }
    }
#pragma unroll
    for (int s = 0; s < 4; s++) {
      int v0 = 12 + (s & 1);
#pragma unroll
      for (int j = 0; j < 7; j++) {
        float f = cF0[s][j];
#pragma unroll
        for (int c = 0; c < 3; c++) O[s * 3 + c] += f * X1[(v0 - 2 * j) * 3 + c];
      }
    }
  }
  {
    float X2[42];
    if (interior) {
      const float2* p2 = (const float2*)(g_Y2 + rb + 6 * k - 18);
#pragma unroll
      for (int m = 0; m < 21; m++) ((float2*)X2)[m] = p2[m];
    } else {
#pragma unroll
      for (int v = 0; v < 14; v++) {
        int pr = refl(2 * k - 6 + v, 256);
#pragma unroll
        for (int c = 0; c < 3; c++) X2[v * 3 + c] = g_Y2[rb + pr * 3 + c];
      }
    }
#pragma unroll
    for (int s = 0; s < 4; s++) {
      int v1 = 13 - (s & 1);
#pragma unroll
      for (int j = 0; j < 7; j++) {
        float f = cF1[s][j];
#pragma unroll
        for (int c = 0; c < 3; c++) O[s * 3 + c] += f * X2[(v1 - 2 * j) * 3 + c];
      }
    }
  }
  float4* po = (float4*)(g_Z + rb2 + 12 * k);
#pragma unroll
  for (int m = 0; m < 3; m++)
    po[m] = make_float4(O[4 * m], O[4 * m + 1], O[4 * m + 2], O[4 * m + 3]);
}

// ---------------- KB: level-0 fused, tiled 8 rows x 64 cols -----------------
// grid (8, 64, 8); block 256.
// Phase 1: 210 threads compute y1/y2 for 70 halo cols x 3 ch x 8 rows -> smem.
// Phase 2: 256 threads do horizontal biort from smem -> out (6 floats each).
__global__ __launch_bounds__(256) void kB_lvl0(const float* __restrict__ hi0,
                                               float* __restrict__ out) {
  __shared__ float sY1[8][210];
  __shared__ float sY2[8][210];
  int wt = blockIdx.x * 64;
  int rt = blockIdx.y * 8;
  int b  = blockIdx.z;
  int t  = threadIdx.x;

  if (t < 210) {
    int ucol = t / 3, c = t - 3 * ucol;
    int w  = wt - 3 + ucol;
    int wr = refl(w, 512);                 // horizontal reflection folded into halo
    int jj = wr >> 1, wp = wr & 1;
    const float* zb = g_Z + ((b * 512) * 512 + wr) * 3 + c;   // + pr*1536
    const float* hb = hi0 + ((b * 256) * 256 + jj) * 36 + c;  // + i*9216
    const bool vint = (rt >= 4 && rt <= 500);

    float a1[8], a2[8];
#pragma unroll
    for (int s = 0; s < 8; s++) { a1[s] = 0.f; a2[s] = 0.f; }

    // pass A: g0-filtered streams (Z and hl), rows rt-3 .. rt+10
    {
      float xz[14], xhl[14];
#pragma unroll
      for (int v = 0; v < 14; v++) {
        int p = rt - 3 + v;
        int pr = vint ? p : refl(p, 512);
        xz[v] = zb[pr * 1536];
        int i = pr >> 1, rp = pr & 1;
        const float* qq = hb + i * 9216 + ((rp ^ wp) ? 18 : 0);
        xhl[v] = comb(qq[6], qq[9], rp, wp);
      }
#pragma unroll
      for (int s = 0; s < 8; s++)
#pragma unroll
        for (int j = 0; j < 7; j++) {
          float f = cG0[j];
          a1[s] += f * xz [s + 6 - j];
          a2[s] += f * xhl[s + 6 - j];
        }
    }
    // pass B: g1-filtered streams (lh and hh), rows rt-2 .. rt+9
    {
      float xlh[12], xhh[12];
#pragma unroll
      for (int v = 0; v < 12; v++) {
        int p = rt - 2 + v;
        int pr = vint ? p : refl(p, 512);
        int i = pr >> 1, rp = pr & 1;
        const float* qq = hb + i * 9216 + ((rp ^ wp) ? 18 : 0);
        xlh[v] = comb(qq[0], qq[15], rp, wp);
        xhh[v] = comb(qq[3], qq[12], rp, wp);
      }
#pragma unroll
      for (int s = 0; s < 8; s++) {
        float lh = 0.f, hh = 0.f;
#pragma unroll
        for (int j = 0; j < 5; j++) {
          float f = cG1[j];
          lh += f * xlh[s + 4 - j];
          hh += f * xhh[s + 4 - j];
        }
        sY1[s][t] = a1[s] + SCQ * lh;
        sY2[s][t] = SCQ * (a2[s] + hh);
      }
    }
  }
  __syncthreads();

  // phase 2: thread -> (row, 2 cols, 3 ch)
  int row = t >> 5, cp = t & 31;
  int cc0 = 2 * cp;                         // local output col 0..63
  float o[6];
#pragma unroll
  for (int d = 0; d < 2; d++) {
    int cc = cc0 + d;
#pragma unroll
    for (int c = 0; c < 3; c++) {
      float acc = 0.f;
#pragma unroll
      for (int j = 0; j < 7; j++) acc += cG0[j] * sY1[row][(cc + 6 - j) * 3 + c];
#pragma unroll
      for (int j = 0; j < 5; j++) acc += cG1[j] * sY2[row][(cc + 5 - j) * 3 + c];
      o[d * 3 + c] = acc;
    }
  }
  int ob = ((b * 512 + rt + row) * 512 + wt + cc0) * 3;   // even -> float2 aligned
  float2* po = (float2*)(out + ob);
  po[0] = make_float2(o[0], o[1]);
  po[1] = make_float2(o[2], o[3]);
  po[2] = make_float2(o[4], o[5]);
}

extern "C" void kernel_launch(void* const* d_in, const int* in_sizes, int n_in,
                              void* d_out, int out_size) {
  const float *low = nullptr, *high0 = nullptr, *high1 = nullptr;
  for (int i = 0; i < n_in; i++) {
    if (in_sizes[i] == 8 * 256 * 256 * 3)       low   = (const float*)d_in[i];
    else if (in_sizes[i] == 8 * 256 * 256 * 36) high0 = (const float*)d_in[i];
    else if (in_sizes[i] == 8 * 128 * 128 * 36) high1 = (const float*)d_in[i];
  }
  float* out = (float*)d_out;

  k1_lvl1_vert<<<dim3(3, 128, 8), 256>>>(low, high1);
  k2_lvl1_horz<<<2048, 256>>>();                 // 8*512*128 threads
  kB_lvl0<<<dim3(8, 64, 8), 256>>>(high0, out);  // fused level-0
}

// round 7
// speedup vs baseline: 1.2251x; 1.0077x over previous
#include <cuda_runtime.h>

// ---------------------------------------------------------------------------
// Inverse DTCWT, 2 levels.
//   k1/k2: level-1 qshift (vertical 2-pass, then horizontal) via g_Y1/g_Y2 -> g_Z
//   kB   : level-0 biort, fused tiled (vertical->smem->horizontal) -> out
// ---------------------------------------------------------------------------

#define SCQ 0.70710678118654752f

__constant__ float cF0[4][7] = {
  { 0.00325314f,  0.03466035f, -0.11720389f,  0.75614564f,  0.01186609f,  0.02382538f, -0.00543948f},
  {-0.00455690f,  0.01702522f, -0.10671180f,  0.56881042f,  0.27529538f, -0.03887280f, -0.00388321f},
  {-0.00388321f, -0.03887280f,  0.27529538f,  0.56881042f, -0.10671180f,  0.01702522f, -0.00455690f},
  {-0.00543948f,  0.02382538f,  0.01186609f,  0.75614564f, -0.11720389f,  0.03466035f,  0.00325314f}
};
__constant__ float cF1[4][7] = {
  {-0.00455690f,  0.01702522f, -0.10671180f,  0.56881042f,  0.27529538f, -0.03887280f, -0.00388321f},
  {-0.00325314f, -0.03466035f,  0.11720389f, -0.75614564f, -0.01186609f, -0.02382538f,  0.00543948f},
  { 0.00543948f, -0.02382538f, -0.01186609f, -0.75614564f,  0.11720389f, -0.03466035f, -0.00325314f},
  {-0.00388321f, -0.03887280f,  0.27529538f,  0.56881042f, -0.10671180f,  0.01702522f, -0.00455690f}
};
__constant__ float cG0[7] = {-0.0107142857142857f, -0.0535714285714286f, 0.2607142857142857f,
                              0.6071428571428571f,  0.2607142857142857f, -0.0535714285714286f,
                             -0.0107142857142857f};
__constant__ float cG1[5] = {-0.05f, -0.25f, 0.6f, -0.25f, -0.05f};

// scratch
__device__ float g_Y1[8 * 512 * 256 * 3];
__device__ float g_Y2[8 * 512 * 256 * 3];
__device__ float g_Z [8 * 512 * 512 * 3];

__device__ __forceinline__ int refl(int p, int L) {
  return p < 0 ? (-1 - p) : (p >= L ? (2 * L - 1 - p) : p);
}
__device__ __forceinline__ float comb(float x, float y, int rp, int wp) {
  return rp == 0 ? (x + y) : (wp == 0 ? (x - y) : (y - x));
}

// ---------------- K1: level-1 vertical (qshift over H), 2-pass --------------
__global__ __launch_bounds__(256) void k1_lvl1_vert(const float* __restrict__ low,
                                                    const float* __restrict__ hi1) {
  int u = blockIdx.x * 256 + threadIdx.x;   // 0..767 = 3*w+c
  int k = blockIdx.y;                        // 0..127
  int b = blockIdx.z;
  int w = u / 3, c = u - 3 * w;
  int jj = w >> 1, wp = w & 1;
  const bool interior = (k >= 3 && k <= 124);
  const int base = 2 * k - 6;

  const float* lowb = low + ((b * 256) * 256 + w) * 3 + c;
  const float* hb   = hi1 + ((b * 128) * 128 + jj) * 36 + c;

  // precompute reflected row indices once
  int pr[14];
#pragma unroll
  for (int v = 0; v < 14; v++) {
    int p = base + v;
    pr[v] = interior ? p : refl(p, 256);
  }

  float a[4], hl[4];
  // ---- pass A: xl (low) + xhl streams, F0 taps ----
  {
    float xl[14], xhl[14];
#pragma unroll
    for (int v = 0; v < 14; v++) {
      int p = pr[v];
      xl[v] = lowb[p * 768];
      int i = p >> 1, rp = p & 1;
      const float* q = hb + i * 4608 + ((rp ^ wp) ? 18 : 0);
      xhl[v] = comb(q[6], q[9], rp, wp);
    }
#pragma unroll
    for (int s = 0; s < 4; s++) {
      int v0 = 12 + (s & 1);
      float aa = 0.f, hh = 0.f;
#pragma unroll
      for (int j = 0; j < 7; j++) {
        float f = cF0[s][j];
        aa += f * xl [v0 - 2*j];
        hh += f * xhl[v0 - 2*j];
      }
      a[s] = aa; hl[s] = hh;
    }
  }
  // ---- pass B: xlh + xhh streams, F1 taps; emit ----
  {
    float xlh[14], xhh[14];
#pragma unroll
    for (int v = 0; v < 14; v++) {
      int p = pr[v];
      int i = p >> 1, rp = p & 1;
      const float* q = hb + i * 4608 + ((rp ^ wp) ? 18 : 0);
      xlh[v] = comb(q[0], q[15], rp, wp);
      xhh[v] = comb(q[3], q[12], rp, wp);
    }
    int ob = ((b * 512 + 4 * k) * 256 + w) * 3 + c;
#pragma unroll
    for (int s = 0; s < 4; s++) {
      int v1 = 13 - (s & 1);
      float lh = 0.f, hh = 0.f;
#pragma unroll
      for (int j = 0; j < 7; j++) {
        float f = cF1[s][j];
        lh += f * xlh[v1 - 2*j];
        hh += f * xhh[v1 - 2*j];
      }
      g_Y1[ob + s * 768] = a[s] + SCQ * lh;
      g_Y2[ob + s * 768] = SCQ * (hl[s] + hh);
    }
  }
}

// ---------------- K2: level-1 horizontal (qshift over W), vectorized --------
__global__ __launch_bounds__(256, 4) void k2_lvl1_horz() {
  int idx = blockIdx.x * 256 + threadIdx.x;
  int k = idx & 127;
  int h = (idx >> 7) & 511;
  int b = idx >> 16;
  const bool interior = (k >= 3 && k <= 124);
  int rb  = ((b * 512 + h) * 256) * 3;
  int rb2 = ((b * 512 + h) * 512) * 3;

  float O[12];
#pragma unroll
  for (int i = 0; i < 12; i++) O[i] = 0.f;

  {
    float X1[42];
    if (interior) {
      const float2* p2 = (const float2*)(g_Y1 + rb + 6 * k - 18);
#pragma unroll
      for (int m = 0; m < 21; m++) ((float2*)X1)[m] = p2[m];
    } else {
#pragma unroll
      for (int v = 0; v < 14; v++) {
        int pr = refl(2 * k - 6 + v, 256);
#pragma unroll
        for (int c = 0; c < 3; c++) X1[v * 3 + c] = g_Y1[rb + pr * 3 + c];
      }
    }
#pragma unroll
    for (int s = 0; s < 4; s++) {
      int v0 = 12 + (s & 1);
#pragma unroll
      for (int j = 0; j < 7; j++) {
        float f = cF0[s][j];
#pragma unroll
        for (int c = 0; c < 3; c++) O[s * 3 + c] += f * X1[(v0 - 2 * j) * 3 + c];
      }
    }
  }
  {
    float X2[42];
    if (interior) {
      const float2* p2 = (const float2*)(g_Y2 + rb + 6 * k - 18);
#pragma unroll
      for (int m = 0; m < 21; m++) ((float2*)X2)[m] = p2[m];
    } else {
#pragma unroll
      for (int v = 0; v < 14; v++) {
        int pr = refl(2 * k - 6 + v, 256);
#pragma unroll
        for (int c = 0; c < 3; c++) X2[v * 3 + c] = g_Y2[rb + pr * 3 + c];
      }
    }
#pragma unroll
    for (int s = 0; s < 4; s++) {
      int v1 = 13 - (s & 1);
#pragma unroll
      for (int j = 0; j < 7; j++) {
        float f = cF1[s][j];
#pragma unroll
        for (int c = 0; c < 3; c++) O[s * 3 + c] += f * X2[(v1 - 2 * j) * 3 + c];
      }
    }
  }
  float4* po = (float4*)(g_Z + rb2 + 12 * k);
#pragma unroll
  for (int m = 0; m < 3; m++)
    po[m] = make_float4(O[4 * m], O[4 * m + 1], O[4 * m + 2], O[4 * m + 3]);
}

// ---------------- KB: level-0 fused, tiled 8 rows x 64 cols -----------------
__global__ __launch_bounds__(256) void kB_lvl0(const float* __restrict__ hi0,
                                               float* __restrict__ out) {
  __shared__ float sY1[8][210];
  __shared__ float sY2[8][210];
  int wt = blockIdx.x * 64;
  int rt = blockIdx.y * 8;
  int b  = blockIdx.z;
  int t  = threadIdx.x;

  if (t < 210) {
    int ucol = t / 3, c = t - 3 * ucol;
    int w  = wt - 3 + ucol;
    int wr = refl(w, 512);
    int jj = wr >> 1, wp = wr & 1;
    const float* zb = g_Z + ((b * 512) * 512 + wr) * 3 + c;
    const float* hb = hi0 + ((b * 256) * 256 + jj) * 36 + c;
    const bool vint = (rt >= 4 && rt <= 500);

    float a1[8], a2[8];
#pragma unroll
    for (int s = 0; s < 8; s++) { a1[s] = 0.f; a2[s] = 0.f; }

    {
      float xz[14], xhl[14];
#pragma unroll
      for (int v = 0; v < 14; v++) {
        int p = rt - 3 + v;
        int pr = vint ? p : refl(p, 512);
        xz[v] = zb[pr * 1536];
        int i = pr >> 1, rp = pr & 1;
        const float* qq = hb + i * 9216 + ((rp ^ wp) ? 18 : 0);
        xhl[v] = comb(qq[6], qq[9], rp, wp);
      }
#pragma unroll
      for (int s = 0; s < 8; s++)
#pragma unroll
        for (int j = 0; j < 7; j++) {
          float f = cG0[j];
          a1[s] += f * xz [s + 6 - j];
          a2[s] += f * xhl[s + 6 - j];
        }
    }
    {
      float xlh[12], xhh[12];
#pragma unroll
      for (int v = 0; v < 12; v++) {
        int p = rt - 2 + v;
        int pr = vint ? p : refl(p, 512);
        int i = pr >> 1, rp = pr & 1;
        const float* qq = hb + i * 9216 + ((rp ^ wp) ? 18 : 0);
        xlh[v] = comb(qq[0], qq[15], rp, wp);
        xhh[v] = comb(qq[3], qq[12], rp, wp);
      }
#pragma unroll
      for (int s = 0; s < 8; s++) {
        float lh = 0.f, hh = 0.f;
#pragma unroll
        for (int j = 0; j < 5; j++) {
          float f = cG1[j];
          lh += f * xlh[s + 4 - j];
          hh += f * xhh[s + 4 - j];
        }
        sY1[s][t] = a1[s] + SCQ * lh;
        sY2[s][t] = SCQ * (a2[s] + hh);
      }
    }
  }
  __syncthreads();

  int row = t >> 5, cp = t & 31;
  int cc0 = 2 * cp;
  float o[6];
#pragma unroll
  for (int d = 0; d < 2; d++) {
    int cc = cc0 + d;
#pragma unroll
    for (int c = 0; c < 3; c++) {
      float acc = 0.f;
#pragma unroll
      for (int j = 0; j < 7; j++) acc += cG0[j] * sY1[row][(cc + 6 - j) * 3 + c];
#pragma unroll
      for (int j = 0; j < 5; j++) acc += cG1[j] * sY2[row][(cc + 5 - j) * 3 + c];
      o[d * 3 + c] = acc;
    }
  }
  int ob = ((b * 512 + rt + row) * 512 + wt + cc0) * 3;
  float2* po = (float2*)(out + ob);
  po[0] = make_float2(o[0], o[1]);
  po[1] = make_float2(o[2], o[3]);
  po[2] = make_float2(o[4], o[5]);
}

extern "C" void kernel_launch(void* const* d_in, const int* in_sizes, int n_in,
                              void* d_out, int out_size) {
  const float *low = nullptr, *high0 = nullptr, *high1 = nullptr;
  for (int i = 0; i < n_in; i++) {
    if (in_sizes[i] == 8 * 256 * 256 * 3)       low   = (const float*)d_in[i];
    else if (in_sizes[i] == 8 * 256 * 256 * 36) high0 = (const float*)d_in[i];
    else if (in_sizes[i] == 8 * 128 * 128 * 36) high1 = (const float*)d_in[i];
  }
  float* out = (float*)d_out;

  k1_lvl1_vert<<<dim3(3, 128, 8), 256>>>(low, high1);
  k2_lvl1_horz<<<2048, 256>>>();
  kB_lvl0<<<dim3(8, 64, 8), 256>>>(high0, out);
}